// round 13
// baseline (speedup 1.0000x reference)
#include <cuda_runtime.h>
#include <cuda_bf16.h>
#include <math.h>
#include <stdint.h>

// ---------------------------------------------------------------------------
// Token performer block. mma.sync bf16 m16n8k16 everywhere (fp32 accumulate).
// R12: fragment loads via ldmatrix.x4 (6 smem instr/kk vs 12), smem row
// stride 144B (conflict-free under LDSM 8-row phases). 128x128 CTA tiles,
// 2 CTAs/SM, GBK=64, 2-stage cp.async, fused epilogues, deterministic xd.
// ---------------------------------------------------------------------------

#define BTC 50176LL          // B*T
#define TT  3136LL
#define NB  16LL

constexpr long long OFF_H1    = 0;                       // h1 bf16 / kptv partials fp32
constexpr long long OFF_KQV   = OFF_H1    + BTC*512;     // kqv bf16 (half used)
constexpr long long OFF_KP    = OFF_KQV   + BTC*1536;
constexpr long long OFF_QP    = OFF_KP    + BTC*256;
constexpr long long OFF_XDK   = OFF_QP    + BTC*256;
constexpr long long OFF_XDQ   = OFF_XDK   + BTC;
constexpr long long OFF_DV    = OFF_XDQ   + BTC;
constexpr long long OFF_KS    = OFF_DV    + BTC;
constexpr long long OFF_KSP   = OFF_KS    + NB*256;
constexpr long long OFF_VT    = OFF_KSP   + 28LL*NB*256;
constexpr long long OFF_KPT   = OFF_VT    + NB*512*TT;
constexpr long long OFF_KPTV  = OFF_KPT   + NB*256*TT;
constexpr long long OFF_Y     = OFF_KPTV  + NB*512*256;
constexpr long long OFF_XRES  = OFF_Y     + BTC*512;
constexpr long long OFF_H2    = OFF_XRES  + BTC*512;
constexpr long long OFF_HM    = OFF_H2    + BTC*512;
constexpr long long OFF_WKQVT = OFF_HM    + BTC*512;
constexpr long long OFF_WPROJT= OFF_WKQVT + 1536LL*512;
constexpr long long OFF_WM1T  = OFF_WPROJT+ 512LL*512;
constexpr long long OFF_WM2T  = OFF_WM1T  + 512LL*512;
constexpr long long OFF_WRB   = OFF_WM2T  + 512LL*512;   // bf16 w_rand (half used)
constexpr long long OFF_XDP   = OFF_WRB   + 256LL*512;   // xd partials: 8 tiles x BTC
constexpr long long SCRATCH_TOTAL = OFF_XDP + 8LL*BTC;

__device__ __align__(128) float g_scratch[SCRATCH_TOTAL];

// ---------------------------- helpers --------------------------------------
__device__ __forceinline__ void mma_bf16(float c[4], const unsigned a[4], const unsigned b[2]) {
    asm volatile(
        "mma.sync.aligned.m16n8k16.row.col.f32.bf16.bf16.f32 "
        "{%0,%1,%2,%3}, {%4,%5,%6,%7}, {%8,%9}, {%0,%1,%2,%3};\n"
        : "+f"(c[0]), "+f"(c[1]), "+f"(c[2]), "+f"(c[3])
        : "r"(a[0]), "r"(a[1]), "r"(a[2]), "r"(a[3]), "r"(b[0]), "r"(b[1]));
}

#define LDSM_X4(r0, r1, r2, r3, addr) \
    asm volatile("ldmatrix.sync.aligned.m8n8.x4.shared.b16 {%0,%1,%2,%3}, [%4];" \
                 : "=r"(r0), "=r"(r1), "=r"(r2), "=r"(r3) : "r"(addr))

__device__ __forceinline__ void cp_async16(uint32_t saddr, const void* gmem, bool pred) {
    int sz = pred ? 16 : 0;   // src-size 0 => zero-fill, no gmem access
    asm volatile("cp.async.cg.shared.global [%0], [%1], 16, %2;\n"
                 :: "r"(saddr), "l"(gmem), "r"(sz));
}
#define CP_COMMIT() asm volatile("cp.async.commit_group;\n" ::: "memory")
#define CP_WAIT0()  asm volatile("cp.async.wait_group 0;\n" ::: "memory")

__device__ __forceinline__ float gelu_exact(float x) {
    return 0.5f * x * (1.0f + erff(x * 0.7071067811865476f));
}

// ------------------------------ LayerNorm -----------------------------------
__global__ void ln_kernel(const float* __restrict__ in, const float* __restrict__ g,
                          const float* __restrict__ be, __nv_bfloat16* __restrict__ outv) {
    int r = blockIdx.x;
    int t = threadIdx.x;         // 128 threads, 4 floats each
    const float4* p = (const float4*)(in + (size_t)r * 512);
    float4 v = p[t];
    float s  = v.x + v.y + v.z + v.w;
    float sq = v.x*v.x + v.y*v.y + v.z*v.z + v.w*v.w;
    #pragma unroll
    for (int o = 16; o; o >>= 1) {
        s  += __shfl_xor_sync(0xffffffffu, s,  o);
        sq += __shfl_xor_sync(0xffffffffu, sq, o);
    }
    __shared__ float shs[4], shq[4];
    int wid = t >> 5, lane = t & 31;
    if (!lane) { shs[wid] = s; shq[wid] = sq; }
    __syncthreads();
    s  = shs[0] + shs[1] + shs[2] + shs[3];
    sq = shq[0] + shq[1] + shq[2] + shq[3];
    float mu  = s * (1.0f / 512.0f);
    float var = sq * (1.0f / 512.0f) - mu * mu;
    float inv = rsqrtf(var + 1e-5f);
    float4 gg = ((const float4*)g)[t];
    float4 bb = ((const float4*)be)[t];
    float4 o;
    o.x = (v.x - mu) * inv * gg.x + bb.x;
    o.y = (v.y - mu) * inv * gg.y + bb.y;
    o.z = (v.z - mu) * inv * gg.z + bb.z;
    o.w = (v.w - mu) * inv * gg.w + bb.w;
    __nv_bfloat16* ob = outv + (size_t)r * 512 + t * 4;
    *(__nv_bfloat162*)(ob)     = __floats2bfloat162_rn(o.x, o.y);
    *(__nv_bfloat162*)(ob + 2) = __floats2bfloat162_rn(o.z, o.w);
}

// ks partial sums over t-chunks (bf16 kp in, fp32 partials)
__global__ void kpsum_part(const __nv_bfloat16* __restrict__ kp, float* __restrict__ part) {
    int b = blockIdx.y, c = blockIdx.x, m = threadIdx.x;  // 256 threads
    const __nv_bfloat16* p = kp + ((size_t)b * TT + (size_t)c * 112) * 256 + m;
    float s = 0.f;
    #pragma unroll 4
    for (int t = 0; t < 112; t++) s += __bfloat162float(p[(size_t)t * 256]);
    part[((size_t)c * NB + b) * 256 + m] = s;
}

__global__ void kpsum_reduce(const float* __restrict__ part, float* __restrict__ ks) {
    int b = blockIdx.x, m = threadIdx.x;
    float s = 0.f;
    #pragma unroll
    for (int c = 0; c < 28; c++) s += part[((size_t)c * NB + b) * 256 + m];
    ks[b * 256 + m] = s;
}

// D[r] = qp[r,:] . ks[b,:]   (qp bf16)
__global__ void d_kernel(const __nv_bfloat16* __restrict__ qp, const float* __restrict__ ks,
                         float* __restrict__ D) {
    int r = blockIdx.x * 8 + (threadIdx.x >> 5);
    int lane = threadIdx.x & 31;
    int b = r / (int)TT;
    const __nv_bfloat16* q = qp + (size_t)r * 256;
    const float* s = ks + b * 256;
    float acc = 0.f;
    #pragma unroll
    for (int j = lane; j < 256; j += 32) acc += __bfloat162float(q[j]) * s[j];
    #pragma unroll
    for (int o = 16; o; o >>= 1) acc += __shfl_xor_sync(0xffffffffu, acc, o);
    if (!lane) D[r] = acc;
}

// reduce per-tile xd partials: xd = 0.5 * sum of 4 tile partials (fixed order)
__global__ void reduce_xd(const float* __restrict__ part,
                          float* __restrict__ xdk, float* __restrict__ xdq) {
    long long r = (long long)blockIdx.x * 256 + threadIdx.x;
    float sk = part[r] + part[BTC + r] + part[2*BTC + r] + part[3*BTC + r];
    float sq = part[4*BTC + r] + part[5*BTC + r] + part[6*BTC + r] + part[7*BTC + r];
    xdk[r] = 0.5f * sk;
    xdq[r] = 0.5f * sq;
}

// 32x32 tiled transpose, bf16 in -> bf16 out
__global__ void transpose_b2b(const __nv_bfloat16* __restrict__ in, int ldin, long long strIn,
                              __nv_bfloat16* __restrict__ out, int ldout, long long strOut,
                              int rows, int cols) {
    __shared__ __nv_bfloat16 tile[32][34];
    const __nv_bfloat16* inp = in + (size_t)blockIdx.z * strIn;
    __nv_bfloat16* outp = out + (size_t)blockIdx.z * strOut;
    int bx = blockIdx.x * 32, by = blockIdx.y * 32;
    int x = bx + threadIdx.x;
    #pragma unroll
    for (int j = threadIdx.y; j < 32; j += 8) {
        int y = by + j;
        tile[j][threadIdx.x] = (y < rows && x < cols) ? inp[(size_t)y * ldin + x]
                                                      : __float2bfloat16(0.f);
    }
    __syncthreads();
    int ox = by + threadIdx.x;
    #pragma unroll
    for (int j = threadIdx.y; j < 32; j += 8) {
        int oy = bx + j;
        if (oy < cols && ox < rows) outp[(size_t)oy * ldout + ox] = tile[threadIdx.x][j];
    }
}

// merged weight transpose: wkqv/wproj/wm1/wm2 -> bf16 NT form
__global__ void transpose_weights(const float* __restrict__ wkqv,
                                  const float* __restrict__ wproj,
                                  const float* __restrict__ wm1,
                                  const float* __restrict__ wm2,
                                  __nv_bfloat16* __restrict__ okqv,
                                  __nv_bfloat16* __restrict__ oproj,
                                  __nv_bfloat16* __restrict__ om1,
                                  __nv_bfloat16* __restrict__ om2) {
    __shared__ float tile[32][33];
    int bx = blockIdx.x;
    const float* in; int ldin, ct;
    __nv_bfloat16* outb;
    if (bx < 48)      { in = wkqv;  ldin = 1536; ct = bx;      outb = okqv; }
    else if (bx < 64) { in = wproj; ldin = 512;  ct = bx - 48; outb = oproj; }
    else if (bx < 80) { in = wm1;   ldin = 512;  ct = bx - 64; outb = om1; }
    else              { in = wm2;   ldin = 512;  ct = bx - 80; outb = om2; }
    int c0 = ct * 32, r0 = blockIdx.y * 32;
    int x = c0 + threadIdx.x;
    #pragma unroll
    for (int j = threadIdx.y; j < 32; j += 8)
        tile[j][threadIdx.x] = in[(size_t)(r0 + j) * ldin + x];
    __syncthreads();
    int ox = r0 + threadIdx.x;
    #pragma unroll
    for (int j = threadIdx.y; j < 32; j += 8)
        outb[(size_t)(c0 + j) * 512 + ox] = __float2bfloat16(tile[threadIdx.x][j]);
}

// fp32 -> bf16 copy of w_rand (already NT form: [256, 512])
__global__ void convert_wrand(const float* __restrict__ in, __nv_bfloat16* __restrict__ out) {
    int i = blockIdx.x * 256 + threadIdx.x;   // 131072 elems
    out[i] = __float2bfloat16(in[i]);
}

// reduce split-K kptv partials (7 chunks) -> bf16
__global__ void reduce_kptv(const float* __restrict__ part, __nv_bfloat16* __restrict__ out) {
    int idx = blockIdx.x * 256 + threadIdx.x;   // over 16*131072
    float s = 0.f;
    #pragma unroll
    for (int c = 0; c < 7; c++) s += part[(size_t)c * 2097152 + idx];
    out[idx] = __float2bfloat16(s);
}

// ------- bf16 GEMM (NT), 128x128 tile, 2 CTAs/SM, GBK=64, ldmatrix ---------
// EPI: 0 none, 1 +bias (+xd per-tile partial sumsq), 2 gelu(+bias),
//      3 +bias+resid(fp32), 4 exp(v-rowv)/16, 5 /(rowv+eps).
// zdiv: blockIdx.z = kc*zdiv + bz; bz indexes batch strides, kc*K is k-offset.
// smem row stride 144B (36 banks == 4 mod 32): LDSM 8-row phases conflict-free.
// 8 warps: wm = wid&1 (2 x 64 rows), wn = wid>>1 (4 x 32 cols).
#define B16_LD    144            // bytes per smem row
#define B16_BOFF  18432          // 128 * 144
#define B16_STAGE 36864          // A + B tiles
#define B16_SMEM  73728          // 2 stages

template <int EPI, int OB>
__global__ __launch_bounds__(256, 2) void bgemm(
    const __nv_bfloat16* __restrict__ A, int lda, long long strA,
    const __nv_bfloat16* __restrict__ B, int ldb, long long strB,
    void* __restrict__ Cv, int ldc, long long strC,
    int Mdim, int K, int zdiv,
    const float* __restrict__ bias,
    const float* __restrict__ rowv, long long strRow,
    const float* __restrict__ resid, long long strRes,
    float* __restrict__ xdpart) {
    extern __shared__ __align__(16) char smem[];
    __shared__ float sxd[4][128];
    const uint32_t sbase = (uint32_t)__cvta_generic_to_shared(smem);
    const int tid = threadIdx.x;
    const int wid = tid >> 5, lane = tid & 31;
    const int wm = wid & 1, wn = wid >> 1;
    const int grp = lane >> 2, tig = lane & 3;

    const int bz = blockIdx.z % zdiv;
    const int kc = blockIdx.z / zdiv;
    A += (size_t)bz * strA + (size_t)kc * K;
    B += (size_t)bz * strB + (size_t)kc * K;
    if (rowv)  rowv  += (size_t)bz * strRow;
    if (resid) resid += (size_t)bz * strRes;
    const size_t cOff = (size_t)blockIdx.z * strC;

    const int m0 = blockIdx.y * 128;
    const int n0 = blockIdx.x * 128;

    // per-lane ldmatrix address components (bytes)
    // A: lanes 0-15 -> rows 0-15 @ k, lanes 16-31 -> rows 0-15 @ k+8
    const uint32_t laneA = (uint32_t)((lane & 15) * B16_LD + (lane >> 4) * 16);
    // B: lanes 0-7 rows0-7@k, 8-15 rows0-7@k+8, 16-23 rows8-15@k, 24-31 rows8-15@k+8
    const uint32_t laneB = (uint32_t)(B16_BOFF +
                         ((lane & 7) + ((lane >> 4) << 3)) * B16_LD +
                         (((lane >> 3) & 1) << 4));

    // copy map: 8 x 16B per thread per stage (A 1024 chunks, B 1024 chunks)
    uint32_t soff[8];
    const char* gp[8];
    bool pred[8];
    #pragma unroll
    for (int i = 0; i < 8; i++) {
        int q = tid + (i & 3) * 256;               // 0..1023
        int r = q >> 3, kcq = q & 7;
        if (i < 4) {
            soff[i] = (uint32_t)(r * B16_LD + kcq * 16);
            gp[i] = (const char*)(A + (size_t)(m0 + r) * lda + kcq * 8);
            pred[i] = (m0 + r) < Mdim;
        } else {
            soff[i] = (uint32_t)(B16_BOFF + r * B16_LD + kcq * 16);
            gp[i] = (const char*)(B + (size_t)(n0 + r) * ldb + kcq * 8);
            pred[i] = true;
        }
    }

    float acc[4][4][4];
    #pragma unroll
    for (int mi = 0; mi < 4; mi++)
        #pragma unroll
        for (int ni = 0; ni < 4; ni++)
            #pragma unroll
            for (int j = 0; j < 4; j++) acc[mi][ni][j] = 0.f;

    const int nk = K / 64;
    #pragma unroll
    for (int i = 0; i < 8; i++) cp_async16(sbase + soff[i], gp[i], pred[i]);
    CP_COMMIT();

    for (int it = 0; it < nk; it++) {
        CP_WAIT0();
        __syncthreads();
        if (it + 1 < nk) {
            const uint32_t sb1 = sbase + ((it + 1) & 1) * B16_STAGE;
            const int adv = (it + 1) * 128;   // 64 bf16 = 128 bytes
            #pragma unroll
            for (int i = 0; i < 8; i++) cp_async16(sb1 + soff[i], gp[i] + adv, pred[i]);
            CP_COMMIT();
        }
        const uint32_t sbu = sbase + (it & 1) * B16_STAGE;
        #pragma unroll
        for (int kk = 0; kk < 64; kk += 16) {
            unsigned af[4][4], bf[4][2];
            #pragma unroll
            for (int mi = 0; mi < 4; mi++) {
                uint32_t ad = sbu + (uint32_t)((wm * 64 + mi * 16) * B16_LD + kk * 2) + laneA;
                LDSM_X4(af[mi][0], af[mi][1], af[mi][2], af[mi][3], ad);
            }
            #pragma unroll
            for (int n2 = 0; n2 < 2; n2++) {
                uint32_t ad = sbu + (uint32_t)((wn * 32 + n2 * 16) * B16_LD + kk * 2) + laneB;
                unsigned r0, r1, r2, r3;
                LDSM_X4(r0, r1, r2, r3, ad);
                bf[2 * n2][0] = r0;     bf[2 * n2][1] = r1;
                bf[2 * n2 + 1][0] = r2; bf[2 * n2 + 1][1] = r3;
            }
            #pragma unroll
            for (int mi = 0; mi < 4; mi++)
                #pragma unroll
                for (int ni = 0; ni < 4; ni++)
                    mma_bf16(acc[mi][ni], af[mi], bf[ni]);
        }
    }

    // epilogue (+ optional per-tile xd partial sumsq)
    #pragma unroll
    for (int mi = 0; mi < 4; mi++) {
        #pragma unroll
        for (int half = 0; half < 2; half++) {
            int r = m0 + wm * 64 + mi * 16 + grp + half * 8;
            float ss = 0.f;
            if (r < Mdim) {
                float invd = 0.f, rv = 0.f;
                if (EPI == 5) invd = 1.0f / (rowv[r] + 1e-8f);
                if (EPI == 4) rv = rowv[r];
                #pragma unroll
                for (int ni = 0; ni < 4; ni++) {
                    int c = n0 + wn * 32 + ni * 8 + tig * 2;
                    float v0 = acc[mi][ni][half * 2 + 0];
                    float v1 = acc[mi][ni][half * 2 + 1];
                    if (EPI == 1 || EPI == 2 || EPI == 3) { v0 += bias[c]; v1 += bias[c + 1]; }
                    if (EPI == 2) { v0 = gelu_exact(v0); v1 = gelu_exact(v1); }
                    if (EPI == 3) {
                        float2 rr = *(const float2*)(resid + (size_t)r * ldc + c);
                        v0 += rr.x; v1 += rr.y;
                    }
                    if (EPI == 4) {
                        v0 = expf(v0 - rv) * 0.0625f;
                        v1 = expf(v1 - rv) * 0.0625f;
                    }
                    if (EPI == 5) { v0 *= invd; v1 *= invd; }
                    if (EPI == 1) ss += v0 * v0 + v1 * v1;
                    if (OB) {
                        __nv_bfloat16* cp = (__nv_bfloat16*)Cv + cOff + (size_t)r * ldc + c;
                        *(__nv_bfloat162*)cp = __floats2bfloat162_rn(v0, v1);
                    } else {
                        float* cp = (float*)Cv + cOff + (size_t)r * ldc + c;
                        *(float2*)cp = make_float2(v0, v1);
                    }
                }
            }
            if (EPI == 1) {
                ss += __shfl_xor_sync(0xffffffffu, ss, 1);
                ss += __shfl_xor_sync(0xffffffffu, ss, 2);
                if (tig == 0) sxd[wn][wm * 64 + mi * 16 + grp + half * 8] = ss;
            }
        }
    }
    if (EPI == 1) {
        __syncthreads();
        int tile = n0 >> 7;              // 0..3 k, 4..7 q, 8..11 v
        if (tile < 8 && tid < 128 && (m0 + tid) < Mdim) {
            float s = sxd[0][tid] + sxd[1][tid] + sxd[2][tid] + sxd[3][tid];
            xdpart[(size_t)tile * BTC + m0 + tid] = s;   // written exactly once
        }
    }
}

// ------------------------------- driver -------------------------------------
extern "C" void kernel_launch(void* const* d_in, const int* in_sizes, int n_in,
                              void* d_out, int out_size) {
    const float* x      = (const float*)d_in[0];
    const float* w_kqv  = (const float*)d_in[1];
    const float* b_kqv  = (const float*)d_in[2];
    const float* w_proj = (const float*)d_in[3];
    const float* b_proj = (const float*)d_in[4];
    const float* g1     = (const float*)d_in[5];
    const float* be1    = (const float*)d_in[6];
    const float* g2     = (const float*)d_in[7];
    const float* be2    = (const float*)d_in[8];
    const float* w_mlp1 = (const float*)d_in[9];
    const float* b_mlp1 = (const float*)d_in[10];
    const float* w_mlp2 = (const float*)d_in[11];
    const float* b_mlp2 = (const float*)d_in[12];
    const float* w_rand = (const float*)d_in[13];
    float* out = (float*)d_out;

    float* S = nullptr;
    cudaGetSymbolAddress((void**)&S, g_scratch);

    __nv_bfloat16* h1b   = (__nv_bfloat16*)(S + OFF_H1);
    float* kpart  = S + OFF_H1;               // reused after kqv consumes h1
    __nv_bfloat16* kqvb  = (__nv_bfloat16*)(S + OFF_KQV);
    __nv_bfloat16* kpb   = (__nv_bfloat16*)(S + OFF_KP);
    float* xdk    = S + OFF_XDK;
    float* xdq    = S + OFF_XDQ;
    float* Dv     = S + OFF_DV;
    float* ks     = S + OFF_KS;
    float* ksp    = S + OFF_KSP;
    __nv_bfloat16* vTb   = (__nv_bfloat16*)(S + OFF_VT);
    __nv_bfloat16* kpTb  = (__nv_bfloat16*)(S + OFF_KPT);
    __nv_bfloat16* kptvb = (__nv_bfloat16*)(S + OFF_KPTV);
    __nv_bfloat16* yb    = (__nv_bfloat16*)(S + OFF_Y);
    float* xres   = S + OFF_XRES;
    __nv_bfloat16* h2b   = (__nv_bfloat16*)(S + OFF_H2);
    __nv_bfloat16* hmb   = (__nv_bfloat16*)(S + OFF_HM);
    __nv_bfloat16* wkqvTb  = (__nv_bfloat16*)(S + OFF_WKQVT);
    __nv_bfloat16* wprojTb = (__nv_bfloat16*)(S + OFF_WPROJT);
    __nv_bfloat16* wm1Tb   = (__nv_bfloat16*)(S + OFF_WM1T);
    __nv_bfloat16* wm2Tb   = (__nv_bfloat16*)(S + OFF_WM2T);
    __nv_bfloat16* wrandb  = (__nv_bfloat16*)(S + OFF_WRB);
    float* xdpart = S + OFF_XDP;

    // qp lives right after kp: stride BTC*512 bf16 elems (merged z launch)
    __nv_bfloat16* qpb = kpb + (size_t)BTC * 512;

    cudaFuncSetAttribute(bgemm<1,1>, cudaFuncAttributeMaxDynamicSharedMemorySize, B16_SMEM);
    cudaFuncSetAttribute(bgemm<4,1>, cudaFuncAttributeMaxDynamicSharedMemorySize, B16_SMEM);
    cudaFuncSetAttribute(bgemm<0,0>, cudaFuncAttributeMaxDynamicSharedMemorySize, B16_SMEM);
    cudaFuncSetAttribute(bgemm<5,1>, cudaFuncAttributeMaxDynamicSharedMemorySize, B16_SMEM);
    cudaFuncSetAttribute(bgemm<3,0>, cudaFuncAttributeMaxDynamicSharedMemorySize, B16_SMEM);
    cudaFuncSetAttribute(bgemm<2,1>, cudaFuncAttributeMaxDynamicSharedMemorySize, B16_SMEM);

    const int BT = (int)BTC;
    const float* nullf = nullptr;
    float* nullx = nullptr;
    dim3 tb(32, 8);

    // 1. h1 = LN(x)  (bf16)
    ln_kernel<<<BT, 128>>>(x, g1, be1, h1b);

    // 2. weight transposes (bf16) + w_rand bf16 copy
    transpose_weights<<<dim3(96, 16), tb>>>(w_kqv, w_proj, w_mlp1, w_mlp2,
                                            wkqvTb, wprojTb, wm1Tb, wm2Tb);
    convert_wrand<<<512, 256>>>(w_rand, wrandb);

    // 3. kqv = h1 @ w_kqv + b_kqv  (bf16 out) + per-tile xd partials
    bgemm<1,1><<<dim3(12, 392, 1), 256, B16_SMEM>>>(h1b, 512, 0, wkqvTb, 512, 0,
                                                    kqvb, 1536, 0, BT, 512, 1,
                                                    b_kqv, nullf, 0, nullf, 0,
                                                    xdpart);

    // 4. xd = 0.5 * sum of 4 tile partials each (deterministic fixed order)
    reduce_xd<<<196, 256>>>(xdpart, xdk, xdq);

    // 5. kp/qp = exp((k|q) @ w_rand^T - xd)/16  (merged; z%2: 0->k, 1->q)
    bgemm<4,1><<<dim3(2, 392, 2), 256, B16_SMEM>>>(kqvb, 1536, 512, wrandb, 512, 0,
                                                   kpb, 256, (long long)BTC * 512,
                                                   BT, 512, 2,
                                                   nullf, xdk, BTC, nullf, 0,
                                                   nullx);

    // 6. ks = sum_t kp
    kpsum_part<<<dim3(28, 16), 256>>>(kpb, ksp);
    kpsum_reduce<<<16, 256>>>(ksp, ks);

    // 7. D = qp . ks
    d_kernel<<<BT / 8, 256>>>(qpb, ks, Dv);

    // 8. transposes into K-major bf16
    transpose_b2b<<<dim3(16, 98, 16), tb>>>(kqvb + 1024, 1536, TT * 1536,
                                            vTb, (int)TT, 512 * TT, (int)TT, 512);
    transpose_b2b<<<dim3(8, 98, 16), tb>>>(kpb, 256, TT * 256,
                                           kpTb, (int)TT, 256 * TT, (int)TT, 256);

    // 9. kptv split-K x7: partials (fp32) then reduce -> bf16
    bgemm<0,0><<<dim3(2, 4, 112), 256, B16_SMEM>>>(vTb, (int)TT, 512 * TT,
                                                   kpTb, (int)TT, 256 * TT,
                                                   kpart, 256, 131072, 512, 448, 16,
                                                   nullf, nullf, 0, nullf, 0,
                                                   nullx);
    reduce_kptv<<<8192, 256>>>(kpart, kptvb);

    // 10. y[b] = (qp @ kptv^T) / (D + eps)  (bf16)
    bgemm<5,1><<<dim3(4, 25, 16), 256, B16_SMEM>>>(qpb, 256, TT * 256,
                                                   kptvb, 256, 512 * 256,
                                                   yb, 512, TT * 512, (int)TT, 256, 16,
                                                   nullf, Dv, TT, nullf, 0,
                                                   nullx);

    // 11. xres = x + y @ w_proj + b_proj  (fp32 out)
    bgemm<3,0><<<dim3(4, 392, 1), 256, B16_SMEM>>>(yb, 512, 0, wprojTb, 512, 0,
                                                   xres, 512, 0, BT, 512, 1,
                                                   b_proj, nullf, 0, x, 0,
                                                   nullx);

    // 12. h2 = LN(xres)  (bf16)
    ln_kernel<<<BT, 128>>>(xres, g2, be2, h2b);

    // 13. hm = gelu(h2 @ w_mlp1 + b_mlp1)  (bf16)
    bgemm<2,1><<<dim3(4, 392, 1), 256, B16_SMEM>>>(h2b, 512, 0, wm1Tb, 512, 0,
                                                   hmb, 512, 0, BT, 512, 1,
                                                   b_mlp1, nullf, 0, nullf, 0,
                                                   nullx);

    // 14. out = xres + hm @ w_mlp2 + b_mlp2  (fp32 out)
    bgemm<3,0><<<dim3(4, 392, 1), 256, B16_SMEM>>>(hmb, 512, 0, wm2Tb, 512, 0,
                                                   out, 512, 0, BT, 512, 1,
                                                   b_mlp2, nullf, 0, xres, 0,
                                                   nullx);
}